// round 12
// baseline (speedup 1.0000x reference)
#include <cuda_runtime.h>

#define M 32
#define E_CONST 2.718281828459045f
#define NB_MIN 128   // partial-min blocks

typedef unsigned long long u64;

// scratch: per-block partial column minima (always fully overwritten -> no init)
__device__ float g_part[NB_MIN][M];

// MUFU.EX2 — fast exp2 (no __exp2f intrinsic exists; this is the HW op)
__device__ __forceinline__ float ex2(float x) {
    float r;
    asm("ex2.approx.f32 %0, %1;" : "=f"(r) : "f"(x));
    return r;
}

// ---- packed f32x2 ops (sm_103a; ptxas never auto-generates these) ----
__device__ __forceinline__ u64 pack2(float lo, float hi) {
    u64 r; asm("mov.b64 %0, {%1, %2};" : "=l"(r) : "f"(lo), "f"(hi)); return r;
}
__device__ __forceinline__ void unpack2(u64 v, float& lo, float& hi) {
    asm("mov.b64 {%0, %1}, %2;" : "=f"(lo), "=f"(hi) : "l"(v));
}
__device__ __forceinline__ u64 add2(u64 a, u64 b) {
    u64 r; asm("add.rn.f32x2 %0, %1, %2;" : "=l"(r) : "l"(a), "l"(b)); return r;
}
__device__ __forceinline__ u64 fma2(u64 a, u64 b, u64 c) {
    u64 r; asm("fma.rn.f32x2 %0, %1, %2, %3;" : "=l"(r) : "l"(a), "l"(b), "l"(c)); return r;
}

// K1: partial column-wise min over row stripes. 128 blocks x 256 threads.
__global__ void __launch_bounds__(256) col_min_partial_kernel(
    const float* __restrict__ phi, int n_rows)
{
    const int lane = threadIdx.x & 31;
    const int warp = threadIdx.x >> 5;
    float local = 3.4e38f;
    int gw = blockIdx.x * 8 + warp;
    int nw = NB_MIN * 8;
    for (int r = gw; r < n_rows; r += nw) {
        local = fminf(local, phi[r * M + lane]);
    }
    __shared__ float smin[8][M];
    smin[warp][lane] = local;
    __syncthreads();
    if (threadIdx.x < M) {
        float m = smin[0][lane];
#pragma unroll
        for (int k = 1; k < 8; k++) m = fminf(m, smin[k][lane]);
        g_part[blockIdx.x][lane] = m;
    }
}

// K2: one warp per TWO rows; lane = mode index i.
// launch_bounds(256,8): 8 blocks/SM = 64 warps; grid 1184 = 148*8 = one wave.
__global__ void __launch_bounds__(256, 8) energy_kernel(
    const float* __restrict__ phi,
    const float* __restrict__ Gamma,
    const float* __restrict__ w,
    float* __restrict__ alphas,
    float* __restrict__ logits,
    int n_rows)
{
    const int lane = threadIdx.x & 31;
    const int warp = threadIdx.x >> 5;

    // --- preamble A: reduce 128 partial minima to the global per-mode min ---
    __shared__ float sred[8][M];
    {
        float m = 3.4e38f;
#pragma unroll
        for (int k = 0; k < 16; k++)
            m = fminf(m, g_part[warp * 16 + k][lane]);
        sred[warp][lane] = m;
    }

    // --- preamble B: NEGATED symmetric Gamma, duplicated into f32x2 halves ---
    // ngq[j>>1][i] = ( -G(i,j), -G(i,j), -G(i,j+1), -G(i,j+1) )
    // hot loop reads one LDS.128 per lane per 2 j's; 16B lane stride: conflict-free
    __shared__ ulonglong2 ngq[M / 2][M];
    for (int t = threadIdx.x; t < M * M; t += 256) {
        int i = t & 31, j = t >> 5;           // logical (i, j)
        float v = -((i < j) ? Gamma[i * M + j] : Gamma[j * M + i]);
        ((u64*)&ngq[j >> 1][i])[j & 1] = pack2(v, v);
    }
    __syncthreads();

    float mmin;
    {
        float m = sred[0][lane];
#pragma unroll
        for (int k = 1; k < 8; k++) m = fminf(m, sred[k][lane]);
        mmin = m;
    }
    const float wi = w[lane];

    // double-buffered per-warp broadcast: lj2 = (lj_row0, lj_row1) packed
    __shared__ u64 lsh[8][2][M];

    const float neg_t = -0.17677669529663687f;  // -1/sqrt(32)
    const int stride = gridDim.x * 16;
    int r = (blockIdx.x * 8 + warp) * 2;
    int par = 0;

    if (r < n_rows) {
        // prime the software pipeline (n_rows is even: r+1 valid)
        float p0 = phi[r * M + lane];
        float p1 = phi[(r + 1) * M + lane];

        for (; r < n_rows; r += stride, par ^= 1) {
            // prefetch next pair (clamped index keeps it safe)
            int rn = (r + stride < n_rows) ? r + stride : r;
            float q0 = phi[rn * M + lane];
            float q1 = phi[(rn + 1) * M + lane];

            float phic0 = fmaxf(p0 - mmin + E_CONST, E_CONST);
            float phic1 = fmaxf(p1 - mmin + E_CONST, E_CONST);
            float li0 = __log2f(phic0);
            float li1 = __log2f(phic1);
            lsh[warp][par][lane] = pack2(li0, li1);
            u64 nli2 = pack2(-li0, -li1);
            __syncwarp();

            // sum over ALL j of exp2(l_j + g*(l_i - l_j)) = lj - g*(lj - li);
            // j==i term equals phic_i exactly, so
            // full sum + w_i*phic_i = off-diag + (1+w_i)*phic_i
            float a0 = 0.f, a1 = 0.f, b0 = 0.f, b1 = 0.f;
#pragma unroll
            for (int j = 0; j < M; j += 2) {
                ulonglong2 ng = *(const ulonglong2*)&ngq[j >> 1][lane]; // LDS.128
                u64 ljA = lsh[warp][par][j];      // broadcast LDS.64
                u64 ljB = lsh[warp][par][j + 1];  // broadcast LDS.64
                u64 dA = add2(ljA, nli2);         // lj - li (both rows)
                u64 dB = add2(ljB, nli2);
                u64 argA = fma2(ng.x, dA, ljA);   // lj - g*(lj-li)
                u64 argB = fma2(ng.y, dB, ljB);
                float aA0, aA1, aB0, aB1;
                unpack2(argA, aA0, aA1);
                unpack2(argB, aB0, aB1);
                a0 += ex2(aA0);
                a1 += ex2(aA1);
                b0 += ex2(aB0);
                b1 += ex2(aB1);
            }
            float sum0 = fmaf(wi, phic0, a0 + b0);
            float sum1 = fmaf(wi, phic1, a1 + b1);

            // logits bounded: x in [-71, -15] -> no max-shift needed in f32
            float x0 = neg_t * sum0;
            float x1 = neg_t * sum1;
            float e0 = __expf(x0);
            float e1 = __expf(x1);
            float s0 = e0, s1 = e1;
#pragma unroll
            for (int o = 16; o > 0; o >>= 1) {
                s0 += __shfl_xor_sync(0xffffffffu, s0, o);
                s1 += __shfl_xor_sync(0xffffffffu, s1, o);
            }
            float lg0 = x0 - __logf(s0);
            float lg1 = x1 - __logf(s1);
            float al0 = e0 * __frcp_rn(s0);
            float al1 = e1 * __frcp_rn(s1);

            logits[r * M + lane] = lg0;
            alphas[r * M + lane] = al0;
            logits[(r + 1) * M + lane] = lg1;
            alphas[(r + 1) * M + lane] = al1;

            p0 = q0;
            p1 = q1;
        }
    }
}

extern "C" void kernel_launch(void* const* d_in, const int* in_sizes, int n_in,
                              void* d_out, int out_size) {
    const float* phi   = (const float*)d_in[0];
    const float* Gamma = (const float*)d_in[1];
    const float* w     = (const float*)d_in[2];
    float* out = (float*)d_out;

    int n_rows = in_sizes[0] / M;
    float* alphas = out;
    float* logits = out + (out_size / 2);

    col_min_partial_kernel<<<NB_MIN, 256>>>(phi, n_rows);
    energy_kernel<<<1184, 256>>>(phi, Gamma, w, alphas, logits, n_rows);
}